// round 3
// baseline (speedup 1.0000x reference)
#include <cuda_runtime.h>

#define T_STEPS 512
#define Hdim    512
#define Bsz     256
#define INdim   8
#define NB      128   // CTAs, 1 per SM => co-resident => grid barrier safe
#define NT      256   // threads per CTA

// SMEM layout (float offsets)
#define WH0_OFF 0          // [512][32]  W_hh layer0 slice, k-major, rows interleaved
#define WI1_OFF 16384      // [512][32]  W_ih layer1 slice
#define WH1_OFF 32768      // [512][32]  W_hh layer1 slice
#define WI0_OFF 49152      // [8][32]    W_ih layer0 slice
#define B0_OFF  49408      // [32] combined bias layer0
#define B1_OFF  49440      // [32] combined bias layer1
#define SMEM_FLOATS 49472
#define SMEM_BYTES  (SMEM_FLOATS * 4)   // 197888 B < 227KB opt-in

// ---------------- global scratch (device statics: allocation-free) --------
__device__ float g_h0[2][Hdim][Bsz];   // layer0 h, double buffered, [col][batch]
__device__ float g_h1[2][Hdim][Bsz];   // layer1 h
__device__ float g_fch[256][Bsz];      // fc0 activations [row][batch]
__device__ unsigned g_arrive = 0;      // barrier arrive counter
__device__ unsigned g_gen    = 0;      // barrier release generation

// ---------------- f32x2 packed helpers ------------------------------------
__device__ __forceinline__ unsigned long long pack2(float x) {
    unsigned long long r;
    asm("mov.b64 %0, {%1,%2};" : "=l"(r)
        : "r"(__float_as_uint(x)), "r"(__float_as_uint(x)));
    return r;
}
__device__ __forceinline__ float2 unpack2(unsigned long long v) {
    unsigned lo, hi;
    asm("mov.b64 {%0,%1}, %2;" : "=r"(lo), "=r"(hi) : "l"(v));
    return make_float2(__uint_as_float(lo), __uint_as_float(hi));
}
__device__ __forceinline__ void fma2(unsigned long long& a,
                                     unsigned long long w,
                                     unsigned long long h) {
    asm("fma.rn.f32x2 %0, %1, %2, %0;" : "+l"(a) : "l"(w), "l"(h));
}
__device__ __forceinline__ float sigx(float x) { return 1.0f / (1.0f + __expf(-x)); }

// ---------------- software grid barrier (generation counter) --------------
// Snapshot-based: correct for any number of barriers and across graph replays.
__device__ __forceinline__ void grid_barrier() {
    __syncthreads();
    if (threadIdx.x == 0) {
        __threadfence();
        volatile unsigned* genp = &g_gen;
        unsigned snap = *genp;
        unsigned old = atomicAdd(&g_arrive, 1u);
        if (old == (unsigned)(NB - 1)) {
            g_arrive = 0u;       // safe: all other blocks are spinning on g_gen
            __threadfence();
            atomicAdd(&g_gen, 1u);
        } else {
            while (*genp == snap) { }
        }
        __threadfence();
    }
    __syncthreads();
}

// ---------------- one pipelined tick ---------------------------------------
// Tick t: layer0 step t (if DOL0; recurrent term if DWH0) and
//         layer1 step t-1 (if DOL1; recurrent term if DWH1).
template<bool DOL0, bool DWH0, bool DOL1, bool DWH1>
__device__ __forceinline__ void tick(
    int t, int b1, int rbase, int j0,
    const float* __restrict__ Wh0s, const float* __restrict__ Wi1s,
    const float* __restrict__ Wh1s, const float* __restrict__ Wi0s,
    const float* __restrict__ B0s,  const float* __restrict__ B1s,
    const float* __restrict__ u,
    float* c0, float* c1)
{
    const int b2  = b1 + 64;
    const int pr  = (t - 1) & 1;   // parity of h0_{t-1} (read by both layers)
    const int p1r = t & 1;         // parity of h1_{t-2}
    const int pw0 = t & 1;         // write parity for h0_t
    const int pw1 = (t - 1) & 1;   // write parity for h1_{t-1}

    unsigned long long a0[8], a1[8];

    if (DOL0) {
        const ulonglong2* bp = (const ulonglong2*)(B0s + rbase);
        ulonglong2 q0 = bp[0], q1 = bp[1];
        a0[0]=q0.x; a0[1]=q0.y; a0[2]=q1.x; a0[3]=q1.y;
        a0[4]=q0.x; a0[5]=q0.y; a0[6]=q1.x; a0[7]=q1.y;
        // input projection (IN=8, trivial)
        const float4* xp1 = (const float4*)(u + ((size_t)b1 * T_STEPS + t) * INdim);
        const float4* xp2 = (const float4*)(u + ((size_t)b2 * T_STEPS + t) * INdim);
        float4 xa = xp1[0], xb = xp1[1], xc = xp2[0], xd = xp2[1];
        float xs1[8] = {xa.x, xa.y, xa.z, xa.w, xb.x, xb.y, xb.z, xb.w};
        float xs2[8] = {xc.x, xc.y, xc.z, xc.w, xd.x, xd.y, xd.z, xd.w};
        #pragma unroll
        for (int kk = 0; kk < INdim; ++kk) {
            const ulonglong2* wv = (const ulonglong2*)(Wi0s + kk * 32 + rbase);
            ulonglong2 w0 = wv[0], w1 = wv[1];
            unsigned long long hx1 = pack2(xs1[kk]);
            unsigned long long hx2 = pack2(xs2[kk]);
            fma2(a0[0], w0.x, hx1); fma2(a0[1], w0.y, hx1);
            fma2(a0[2], w1.x, hx1); fma2(a0[3], w1.y, hx1);
            fma2(a0[4], w0.x, hx2); fma2(a0[5], w0.y, hx2);
            fma2(a0[6], w1.x, hx2); fma2(a0[7], w1.y, hx2);
        }
    }
    if (DOL1) {
        const ulonglong2* bp = (const ulonglong2*)(B1s + rbase);
        ulonglong2 q0 = bp[0], q1 = bp[1];
        a1[0]=q0.x; a1[1]=q0.y; a1[2]=q1.x; a1[3]=q1.y;
        a1[4]=q0.x; a1[5]=q0.y; a1[6]=q1.x; a1[7]=q1.y;
    }

    if (DWH0 || DOL1) {
        const float* __restrict__ h0p = &g_h0[pr][0][0];
        const float* __restrict__ h1p = &g_h1[p1r][0][0];
        #pragma unroll 4
        for (int k = 0; k < Hdim; ++k) {
            float v1 = __ldcg(h0p + k * Bsz + b1);
            float v2 = __ldcg(h0p + k * Bsz + b2);
            unsigned long long hh1 = pack2(v1);
            unsigned long long hh2 = pack2(v2);
            if (DWH0) {
                const ulonglong2* wv = (const ulonglong2*)(Wh0s + k * 32 + rbase);
                ulonglong2 w0 = wv[0], w1 = wv[1];
                fma2(a0[0], w0.x, hh1); fma2(a0[1], w0.y, hh1);
                fma2(a0[2], w1.x, hh1); fma2(a0[3], w1.y, hh1);
                fma2(a0[4], w0.x, hh2); fma2(a0[5], w0.y, hh2);
                fma2(a0[6], w1.x, hh2); fma2(a0[7], w1.y, hh2);
            }
            if (DOL1) {
                const ulonglong2* wv = (const ulonglong2*)(Wi1s + k * 32 + rbase);
                ulonglong2 w0 = wv[0], w1 = wv[1];
                fma2(a1[0], w0.x, hh1); fma2(a1[1], w0.y, hh1);
                fma2(a1[2], w1.x, hh1); fma2(a1[3], w1.y, hh1);
                fma2(a1[4], w0.x, hh2); fma2(a1[5], w0.y, hh2);
                fma2(a1[6], w1.x, hh2); fma2(a1[7], w1.y, hh2);
                if (DWH1) {
                    float g1 = __ldcg(h1p + k * Bsz + b1);
                    float g2 = __ldcg(h1p + k * Bsz + b2);
                    unsigned long long gg1 = pack2(g1);
                    unsigned long long gg2 = pack2(g2);
                    const ulonglong2* uv = (const ulonglong2*)(Wh1s + k * 32 + rbase);
                    ulonglong2 u0 = uv[0], u1 = uv[1];
                    fma2(a1[0], u0.x, gg1); fma2(a1[1], u0.y, gg1);
                    fma2(a1[2], u1.x, gg1); fma2(a1[3], u1.y, gg1);
                    fma2(a1[4], u0.x, gg2); fma2(a1[5], u0.y, gg2);
                    fma2(a1[6], u1.x, gg2); fma2(a1[7], u1.y, gg2);
                }
            }
        }
    }

    // activations + cell update + h writes (each (col,batch) owned by 1 thread)
    if (DOL0) {
        #pragma unroll
        for (int bi = 0; bi < 2; ++bi) {
            int b = bi ? b2 : b1;
            #pragma unroll
            for (int cc = 0; cc < 2; ++cc) {
                float2 ifp = unpack2(a0[bi * 4 + cc * 2 + 0]);
                float2 gop = unpack2(a0[bi * 4 + cc * 2 + 1]);
                float ig = sigx(ifp.x), fg = sigx(ifp.y);
                float gg = tanhf(gop.x), og = sigx(gop.y);
                float c = fg * c0[bi * 2 + cc] + ig * gg;
                c0[bi * 2 + cc] = c;
                float h = og * tanhf(c);
                int j = j0 + (rbase >> 2) + cc;
                __stcg(&g_h0[pw0][j][b], h);
            }
        }
    }
    if (DOL1) {
        #pragma unroll
        for (int bi = 0; bi < 2; ++bi) {
            int b = bi ? b2 : b1;
            #pragma unroll
            for (int cc = 0; cc < 2; ++cc) {
                float2 ifp = unpack2(a1[bi * 4 + cc * 2 + 0]);
                float2 gop = unpack2(a1[bi * 4 + cc * 2 + 1]);
                float ig = sigx(ifp.x), fg = sigx(ifp.y);
                float gg = tanhf(gop.x), og = sigx(gop.y);
                float c = fg * c1[bi * 2 + cc] + ig * gg;
                c1[bi * 2 + cc] = c;
                float h = og * tanhf(c);
                int j = j0 + (rbase >> 2) + cc;
                __stcg(&g_h1[pw1][j][b], h);
            }
        }
    }
}

// ---------------------------------------------------------------------------
__global__ void __launch_bounds__(NT, 1)
lstm_persistent(const float* __restrict__ u,
                const float* __restrict__ wih0, const float* __restrict__ whh0,
                const float* __restrict__ bih0, const float* __restrict__ bhh0,
                const float* __restrict__ wih1, const float* __restrict__ whh1,
                const float* __restrict__ bih1, const float* __restrict__ bhh1,
                const float* __restrict__ fcw0, const float* __restrict__ fcb0,
                const float* __restrict__ fcw1, const float* __restrict__ fcb1,
                float* __restrict__ out)
{
    extern __shared__ float smem[];
    float* Wh0s = smem + WH0_OFF;
    float* Wi1s = smem + WI1_OFF;
    float* Wh1s = smem + WH1_OFF;
    float* Wi0s = smem + WI0_OFF;
    float* B0s  = smem + B0_OFF;
    float* B1s  = smem + B1_OFF;

    const int tid = threadIdx.x;
    const int cg  = blockIdx.x >> 1;     // column group 0..63
    const int bg  = blockIdx.x & 1;      // batch half
    const int j0  = cg * 8;              // first hidden column of slice
    const int rq  = tid >> 6;            // row quarter 0..3 (8 gate rows each)
    const int bq  = tid & 63;            // batch lane
    const int rbase = rq * 8;
    const int b1 = bg * 128 + bq;        // batches handled: b1, b1+64

    // ---- one-time weight staging into SMEM ----
    // local gate row r = jj*4 + g  (jj = col within slice, g = i,f,g,o)
    for (int i = tid; i < 32 * Hdim; i += NT) {
        int r = i & 31, k = i >> 5;
        int jj = r >> 2, g = r & 3;
        int grow = g * Hdim + j0 + jj;
        Wh0s[i] = whh0[grow * Hdim + k];
        Wi1s[i] = wih1[grow * Hdim + k];
        Wh1s[i] = whh1[grow * Hdim + k];
    }
    {
        int r = tid & 31, k = tid >> 5;  // 256 threads cover [8][32] exactly
        int jj = r >> 2, g = r & 3;
        int grow = g * Hdim + j0 + jj;
        Wi0s[k * 32 + r] = wih0[grow * INdim + k];
    }
    if (tid < 32) {
        int jj = tid >> 2, g = tid & 3;
        int grow = g * Hdim + j0 + jj;
        B0s[tid] = bih0[grow] + bhh0[grow];
        B1s[tid] = bih1[grow] + bhh1[grow];
    }
    __syncthreads();

    float c0[4] = {0.f, 0.f, 0.f, 0.f};
    float c1[4] = {0.f, 0.f, 0.f, 0.f};

    // ---- pipelined time loop ----
    tick<true, false, false, false>(0, b1, rbase, j0, Wh0s, Wi1s, Wh1s, Wi0s, B0s, B1s, u, c0, c1);
    grid_barrier();
    tick<true, true, true, false>(1, b1, rbase, j0, Wh0s, Wi1s, Wh1s, Wi0s, B0s, B1s, u, c0, c1);
    grid_barrier();
    for (int t = 2; t < T_STEPS; ++t) {
        tick<true, true, true, true>(t, b1, rbase, j0, Wh0s, Wi1s, Wh1s, Wi0s, B0s, B1s, u, c0, c1);
        grid_barrier();
    }
    tick<false, false, true, true>(T_STEPS, b1, rbase, j0, Wh0s, Wi1s, Wh1s, Wi0s, B0s, B1s, u, c0, c1);
    grid_barrier();

    // ---- FC head: stage A  fch[r][b] = tanh(fcw0[r,:] . h1_T[:,b] + fcb0[r]) ----
    {
        int gid = blockIdx.x * NT + tid;     // 0..32767 = 256 rows x 128 bq
        int r  = gid >> 7;
        int bqq = gid & 127;
        const float* __restrict__ wrow  = fcw0 + (size_t)r * Hdim;
        const float* __restrict__ hbase = &g_h1[1][0][0];   // h1_{511} parity
        float acc1 = 0.f, acc2 = 0.f;
        #pragma unroll 4
        for (int k = 0; k < Hdim; ++k) {
            float w = __ldg(wrow + k);
            acc1 += w * __ldcg(hbase + k * Bsz + bqq);
            acc2 += w * __ldcg(hbase + k * Bsz + bqq + 128);
        }
        float bb = __ldg(fcb0 + r);
        __stcg(&g_fch[r][bqq],       tanhf(acc1 + bb));
        __stcg(&g_fch[r][bqq + 128], tanhf(acc2 + bb));
    }
    grid_barrier();

    // ---- stage B (block 0): out[b][c] and final affine ----
    if (blockIdx.x == 0) {
        int b = tid;                     // 0..255
        float s0 = __ldg(fcb1 + 0), s1 = __ldg(fcb1 + 1);
        #pragma unroll 4
        for (int k = 0; k < 256; ++k) {
            float v = __ldcg(&g_fch[k][b]);
            s0 += v * __ldg(fcw1 + k);
            s1 += v * __ldg(fcw1 + 256 + k);
        }
        const float scale = 0.5f * (4.2f - 2.5f);
        out[b * 2 + 0] = (s0 + 1.0f) * scale + 2.5f;
        out[b * 2 + 1] = (s1 + 1.0f) * scale + 2.5f;
    }
}

// ---------------------------------------------------------------------------
extern "C" void kernel_launch(void* const* d_in, const int* in_sizes, int n_in,
                              void* d_out, int out_size) {
    (void)in_sizes; (void)n_in; (void)out_size;
    const float* u    = (const float*)d_in[0];
    const float* wih0 = (const float*)d_in[1];
    const float* whh0 = (const float*)d_in[2];
    const float* bih0 = (const float*)d_in[3];
    const float* bhh0 = (const float*)d_in[4];
    const float* wih1 = (const float*)d_in[5];
    const float* whh1 = (const float*)d_in[6];
    const float* bih1 = (const float*)d_in[7];
    const float* bhh1 = (const float*)d_in[8];
    const float* fcw0 = (const float*)d_in[9];
    const float* fcb0 = (const float*)d_in[10];
    const float* fcw1 = (const float*)d_in[11];
    const float* fcb1 = (const float*)d_in[12];
    float* out = (float*)d_out;

    cudaFuncSetAttribute(lstm_persistent,
                         cudaFuncAttributeMaxDynamicSharedMemorySize, SMEM_BYTES);
    lstm_persistent<<<NB, NT, SMEM_BYTES>>>(
        u, wih0, whh0, bih0, bhh0, wih1, whh1, bih1, bhh1,
        fcw0, fcb0, fcw1, fcb1, out);
}